// round 4
// baseline (speedup 1.0000x reference)
#include <cuda_runtime.h>
#include <math.h>
#include <stdint.h>

// Problem constants
#define Bn 8
#define Sn 1024
#define En 768
#define Hn 12
#define F3 (3 * En)          // 2304
#define NQKV (Hn * F3)       // 27648
#define HE (Hn * En)         // 9216

// Scratch (allocation-free: __device__ globals)
__device__ float g_qkv[(size_t)Bn * Hn * Sn * F3];     // [B,H,S,3E]
__device__ float g_scores[(size_t)Bn * Hn * Sn * Sn];  // [B*H,S,S]
__device__ float g_vT[(size_t)Bn * Hn * En * Sn];      // [B*H,E,S]
__device__ float g_concat[(size_t)Bn * Sn * Hn * En];  // [B,S,H,E]

struct GemmParams {
    const float* A;   // [M,K] K-major, row stride lda
    const float* B;   // [N,K] K-major, row stride ldb
    float* C;
    int K;
    int lda, ldb, ldc;
    long long strideAz, strideBz;
    long long strideCb, strideCh;
    int divH;
    const float* bias;
    float alpha;
};

__device__ __forceinline__ uint32_t f2tf32(float x) {
    uint32_t r;
    asm("cvt.rna.tf32.f32 %0, %1;" : "=r"(r) : "f"(x));
    return r;
}

__device__ __forceinline__ void mma_tf32(float* d, const uint32_t* a, const uint32_t* b) {
    asm volatile(
        "mma.sync.aligned.m16n8k8.row.col.f32.tf32.tf32.f32 "
        "{%0,%1,%2,%3}, {%4,%5,%6,%7}, {%8,%9}, {%0,%1,%2,%3};"
        : "+f"(d[0]), "+f"(d[1]), "+f"(d[2]), "+f"(d[3])
        : "r"(a[0]), "r"(a[1]), "r"(a[2]), "r"(a[3]), "r"(b[0]), "r"(b[1]));
}

// Tensor-core tf32 GEMM, A[M,K] x B[N,K]^T. Tile 128x128x32.
// 8 warps (2 M x 4 N), warp tile 64x32. 2-stage pipeline:
//   iter kt: issue LDGs for kt+1 -> MMA on buf(kt) -> convert/STS to buf(kt^1) -> sync
// SMEM fragment-order with XOR(kstep) swizzle -> LDS/STS conflict-free.
// Dynamic SMEM: As[2]=2*16KB, Bs[2]=2*16KB = 64KB.
// EPI: 0 = plain C write, 1 = QKV scatter to [B,H,S,3E]
template <int EPI>
__global__ void __launch_bounds__(256) gemm_tc(GemmParams p)
{
    extern __shared__ uint32_t smem[];
    uint32_t* AsBuf[2] = { smem, smem + 4096 };
    uint32_t* BsBuf[2] = { smem + 8192, smem + 12288 };

    const int tid = threadIdx.x;
    const int lane = tid & 31;
    const int wid = tid >> 5;
    const int warp_m = wid & 1;   // 0..1
    const int warp_n = wid >> 1;  // 0..3

    const int bn = blockIdx.x;
    const int bm = blockIdx.y;
    const int z  = blockIdx.z;

    const float* A = p.A + (size_t)z * p.strideAz + (size_t)bm * 128 * p.lda;
    const float* Bp = p.B + (size_t)z * p.strideBz + (size_t)bn * 128 * p.ldb;

    // A thread mapping: 5-bit permutation of row group so each warp's stores
    // cover all 32 banks.
    const int gA = tid >> 3;
    const int col4 = tid & 7;
    const int rowpA = ((gA & 1) << 3) | ((gA >> 1) & 1) | (((gA >> 2) & 1) << 1)
                    | (((gA >> 3) & 1) << 2) | (gA & 16);
    const int kstepL = col4 >> 1;   // k8 step of this thread's float4
    const int chi    = col4 & 1;    // k-half within 8
    const int rowB   = tid >> 3;    // B n-local row (t adds 32)

    float acc[4][4][4];
    #pragma unroll
    for (int i = 0; i < 4; i++)
        #pragma unroll
        for (int j = 0; j < 4; j++)
            #pragma unroll
            for (int r = 0; r < 4; r++) acc[i][j][r] = 0.f;

    float4 aR[4], bR[4];

    auto loadTile = [&](int k0) {
        #pragma unroll
        for (int t = 0; t < 4; t++) {
            aR[t] = *(const float4*)(A + (size_t)(rowpA + 32 * t) * p.lda + k0 + col4 * 4);
            bR[t] = *(const float4*)(Bp + (size_t)(rowB + 32 * t) * p.ldb + k0 + col4 * 4);
        }
    };

    auto storeTile = [&](uint32_t* as, uint32_t* bs) {
        #pragma unroll
        for (int t = 0; t < 4; t++) {
            const int row = rowpA + 32 * t;
            const int mtile = row >> 4;
            const int m8 = row & 7;
            const int reg = ((row >> 3) & 1) + 2 * chi;
            const uint32_t base = (uint32_t)(kstepL * 8 + mtile) * 128 + (m8 >> 1) * 32 + reg;
            float c[4] = {aR[t].x, aR[t].y, aR[t].z, aR[t].w};
            #pragma unroll
            for (int jj = 0; jj < 4; jj++) {
                const int lan = m8 * 4 + jj;
                as[base + (((lan & 7) ^ kstepL) << 2)] = f2tf32(c[jj]);
            }
        }
        #pragma unroll
        for (int t = 0; t < 4; t++) {
            const int row = rowB + 32 * t;
            const int ntile = row >> 3;
            const int n8 = row & 7;
            const uint32_t base = (uint32_t)(kstepL * 16 + ntile) * 64 + ((n8 * 4) >> 4) * 32 + chi;
            float c[4] = {bR[t].x, bR[t].y, bR[t].z, bR[t].w};
            #pragma unroll
            for (int jj = 0; jj < 4; jj++) {
                const int lan = n8 * 4 + jj;
                bs[base + (((lan & 15) ^ kstepL) << 1)] = f2tf32(c[jj]);
            }
        }
    };

    // Prologue: tile 0 into buffer 0
    loadTile(0);
    storeTile(AsBuf[0], BsBuf[0]);
    __syncthreads();

    const int nIter = p.K >> 5;
    for (int kt = 0; kt < nIter; kt++) {
        const int buf = kt & 1;
        if (kt + 1 < nIter) loadTile((kt + 1) << 5);   // LDGs in flight over compute

        const uint32_t* as = AsBuf[buf];
        const uint32_t* bs = BsBuf[buf];
        #pragma unroll
        for (int ks = 0; ks < 4; ks++) {
            uint32_t af[4][4];
            uint32_t bf[4][2];
            #pragma unroll
            for (int mt = 0; mt < 4; mt++) {
                const int frag = ks * 8 + warp_m * 4 + mt;
                uint4 v = *(const uint4*)&as[frag * 128 + (lane >> 3) * 32 +
                                             (((lane & 7) ^ ks) << 2)];
                af[mt][0] = v.x; af[mt][1] = v.y; af[mt][2] = v.z; af[mt][3] = v.w;
            }
            #pragma unroll
            for (int nt = 0; nt < 4; nt++) {
                const int frag = ks * 16 + warp_n * 4 + nt;
                uint2 v = *(const uint2*)&bs[frag * 64 + (lane >> 4) * 32 +
                                             (((lane & 15) ^ ks) << 1)];
                bf[nt][0] = v.x; bf[nt][1] = v.y;
            }
            #pragma unroll
            for (int mt = 0; mt < 4; mt++)
                #pragma unroll
                for (int nt = 0; nt < 4; nt++)
                    mma_tf32(acc[mt][nt], af[mt], bf[nt]);
        }

        if (kt + 1 < nIter) storeTile(AsBuf[buf ^ 1], BsBuf[buf ^ 1]);
        __syncthreads();
    }

    // ---- Epilogue ----
    const size_t coff = (size_t)(z / p.divH) * p.strideCb +
                        (size_t)(z % p.divH) * p.strideCh;
    const int r  = lane >> 2;
    const int c2 = (lane & 3) * 2;

    #pragma unroll
    for (int mt = 0; mt < 4; mt++) {
        #pragma unroll
        for (int nt = 0; nt < 4; nt++) {
            const int n = bn * 128 + warp_n * 32 + nt * 8 + c2;
            float b0 = 0.f, b1 = 0.f;
            if (p.bias) {
                float2 bb = *(const float2*)&p.bias[n];
                b0 = bb.x; b1 = bb.y;
            }
            #pragma unroll
            for (int half = 0; half < 2; half++) {
                const int m = bm * 128 + warp_m * 64 + mt * 16 + r + half * 8;
                const float v0 = acc[mt][nt][half * 2 + 0] * p.alpha + b0;
                const float v1 = acc[mt][nt][half * 2 + 1] * p.alpha + b1;
                if (EPI == 1) {
                    const int b = m >> 10;
                    const int s = m & 1023;
                    const int h = n / F3;
                    const int f = n - h * F3;
                    *(float2*)&g_qkv[(((size_t)(b * Hn + h)) * Sn + s) * F3 + f] =
                        make_float2(v0, v1);
                } else {
                    *(float2*)&p.C[coff + (size_t)m * p.ldc + n] = make_float2(v0, v1);
                }
            }
        }
    }
}

// Transpose V slab of qkv: vT[bh, e, s] = qkv[bh, s, 2E + e]
__global__ void __launch_bounds__(256) transpose_v()
{
    __shared__ float tile[32][33];
    const int bh = blockIdx.z;
    const int s0 = blockIdx.x * 32;
    const int e0 = blockIdx.y * 32;
    const int tx = threadIdx.x;   // 0..31
    const int ty = threadIdx.y;   // 0..7
    const float* src = g_qkv + ((size_t)bh * Sn) * F3 + 2 * En;
    float* dst = g_vT + ((size_t)bh * En) * Sn;

    #pragma unroll
    for (int j = 0; j < 4; j++)
        tile[ty + 8 * j][tx] = src[(size_t)(s0 + ty + 8 * j) * F3 + e0 + tx];
    __syncthreads();
    #pragma unroll
    for (int j = 0; j < 4; j++)
        dst[(size_t)(e0 + ty + 8 * j) * Sn + s0 + tx] = tile[tx][ty + 8 * j];
}

// Softmax over rows of g_scores: one block (256 thr) per 1024-element row.
__global__ void __launch_bounds__(256) softmax_kernel(float* sc)
{
    float* row = sc + (size_t)blockIdx.x * Sn;
    const int tid = threadIdx.x;
    const int lane = tid & 31;
    const int wid = tid >> 5;
    __shared__ float red[8];

    float4 v = ((const float4*)row)[tid];
    float m = fmaxf(fmaxf(v.x, v.y), fmaxf(v.z, v.w));
    #pragma unroll
    for (int o = 16; o; o >>= 1) m = fmaxf(m, __shfl_xor_sync(~0u, m, o));
    if (lane == 0) red[wid] = m;
    __syncthreads();
    float bm = red[0];
    #pragma unroll
    for (int i = 1; i < 8; i++) bm = fmaxf(bm, red[i]);
    __syncthreads();

    float4 e;
    e.x = __expf(v.x - bm);
    e.y = __expf(v.y - bm);
    e.z = __expf(v.z - bm);
    e.w = __expf(v.w - bm);
    float s = e.x + e.y + e.z + e.w;
    #pragma unroll
    for (int o = 16; o; o >>= 1) s += __shfl_xor_sync(~0u, s, o);
    if (lane == 0) red[wid] = s;
    __syncthreads();
    float bs = red[0];
    #pragma unroll
    for (int i = 1; i < 8; i++) bs += red[i];
    const float rdiv = __frcp_rn(bs);

    e.x *= rdiv; e.y *= rdiv; e.z *= rdiv; e.w *= rdiv;
    ((float4*)row)[tid] = e;
}

#define GEMM_SMEM 65536

extern "C" void kernel_launch(void* const* d_in, const int* in_sizes, int n_in,
                              void* d_out, int out_size)
{
    const float* x     = (const float*)d_in[0];  // [B,S,E]
    const float* qkv_w = (const float*)d_in[1];  // [H,3E,E]
    const float* qkv_b = (const float*)d_in[2];  // [H,3E]
    const float* out_w = (const float*)d_in[3];  // [E,H*E]
    const float* out_b = (const float*)d_in[4];  // [E]
    float* out = (float*)d_out;                  // [B,S,E]

    float *qkv, *scores, *vT, *concat;
    cudaGetSymbolAddress((void**)&qkv,    g_qkv);
    cudaGetSymbolAddress((void**)&scores, g_scores);
    cudaGetSymbolAddress((void**)&vT,     g_vT);
    cudaGetSymbolAddress((void**)&concat, g_concat);

    cudaFuncSetAttribute(gemm_tc<0>, cudaFuncAttributeMaxDynamicSharedMemorySize, GEMM_SMEM);
    cudaFuncSetAttribute(gemm_tc<1>, cudaFuncAttributeMaxDynamicSharedMemorySize, GEMM_SMEM);

    // 1) QKV projection: [8192,768] x [27648,768]^T -> scatter [B,H,S,3E], +bias
    {
        GemmParams p = {};
        p.A = x; p.B = qkv_w; p.C = qkv;
        p.K = En; p.lda = En; p.ldb = En; p.ldc = 0;
        p.strideAz = 0; p.strideBz = 0;
        p.strideCb = 0; p.strideCh = 0; p.divH = 1;
        p.bias = qkv_b; p.alpha = 1.0f;
        gemm_tc<1><<<dim3(NQKV / 128, (Bn * Sn) / 128, 1), 256, GEMM_SMEM>>>(p);
    }

    // 1b) Transpose V slab -> vT [B*H, E, S]
    transpose_v<<<dim3(Sn / 32, En / 32, Bn * Hn), dim3(32, 8)>>>();

    // 2) Scores: per (b,h): Q[1024,768] x K[1024,768]^T * scale
    {
        GemmParams p = {};
        p.A = qkv; p.B = qkv + En; p.C = scores;
        p.K = En; p.lda = F3; p.ldb = F3; p.ldc = Sn;
        p.strideAz = (long long)Sn * F3;
        p.strideBz = (long long)Sn * F3;
        p.strideCb = (long long)Sn * Sn; p.strideCh = 0; p.divH = 1;
        p.bias = nullptr; p.alpha = 0.036084391824351615f; // 1/sqrt(768)
        gemm_tc<0><<<dim3(Sn / 128, Sn / 128, Bn * Hn), 256, GEMM_SMEM>>>(p);
    }

    // 3) Softmax rows
    softmax_kernel<<<Bn * Hn * Sn, 256>>>(scores);

    // 4) AV: per (b,h): P[1024,1024] x vT[768,1024]^T -> concat [B,S,H,E]
    {
        GemmParams p = {};
        p.A = scores; p.B = vT; p.C = concat;
        p.K = Sn; p.lda = Sn; p.ldb = Sn; p.ldc = HE;
        p.strideAz = (long long)Sn * Sn;
        p.strideBz = (long long)En * Sn;
        p.strideCb = (long long)Sn * Hn * En;
        p.strideCh = En;
        p.divH = Hn;
        p.bias = nullptr; p.alpha = 1.0f;
        gemm_tc<0><<<dim3(En / 128, Sn / 128, Bn * Hn), 256, GEMM_SMEM>>>(p);
    }

    // 5) Output projection: [8192,9216] x [768,9216]^T + bias -> [8192,768]
    {
        GemmParams p = {};
        p.A = concat; p.B = out_w; p.C = out;
        p.K = HE; p.lda = HE; p.ldb = HE; p.ldc = En;
        p.strideAz = 0; p.strideBz = 0;
        p.strideCb = 0; p.strideCh = 0; p.divH = 1;
        p.bias = out_b; p.alpha = 1.0f;
        gemm_tc<0><<<dim3(En / 128, (Bn * Sn) / 128, 1), 256, GEMM_SMEM>>>(p);
    }
}

// round 5
// speedup vs baseline: 1.0803x; 1.0803x over previous
#include <cuda_runtime.h>
#include <math.h>
#include <stdint.h>

// Problem constants
#define Bn 8
#define Sn 1024
#define En 768
#define Hn 12
#define F3 (3 * En)          // 2304
#define NQKV (Hn * F3)       // 27648
#define HE (Hn * En)         // 9216

// Scratch (allocation-free: __device__ globals)
__device__ float g_qkv[(size_t)Bn * Hn * Sn * F3];     // [B,H,S,3E]
__device__ float g_scores[(size_t)Bn * Hn * Sn * Sn];  // [B*H,S,S]
__device__ float g_vT[(size_t)Bn * Hn * En * Sn];      // [B*H,E,S]
__device__ float g_concat[(size_t)Bn * Sn * Hn * En];  // [B,S,H,E]

struct GemmParams {
    const float* A;   // [M,K] K-major, row stride lda
    const float* B;   // [N,K] K-major, row stride ldb
    float* C;
    int K;
    int lda, ldb, ldc;
    long long strideAz, strideBz;
    long long strideCb, strideCh;
    int divH;
    const float* bias;
    float alpha;
};

__device__ __forceinline__ uint32_t f2tf32(float x) {
    uint32_t r;
    asm("cvt.rna.tf32.f32 %0, %1;" : "=r"(r) : "f"(x));
    return r;
}

__device__ __forceinline__ void mma_tf32(float* d, const uint32_t* a, const uint32_t* b) {
    asm volatile(
        "mma.sync.aligned.m16n8k8.row.col.f32.tf32.tf32.f32 "
        "{%0,%1,%2,%3}, {%4,%5,%6,%7}, {%8,%9}, {%0,%1,%2,%3};"
        : "+f"(d[0]), "+f"(d[1]), "+f"(d[2]), "+f"(d[3])
        : "r"(a[0]), "r"(a[1]), "r"(a[2]), "r"(a[3]), "r"(b[0]), "r"(b[1]));
}

// Tensor-core tf32 GEMM, A[M,K] x B[N,K]^T. Block tile 128x128x32.
// 512 threads = 16 warps (4 M x 4 N), warp tile 32x32 -> 32 acc regs/thread.
// 2-stage pipeline per 32-K iteration:
//   LDG(kt+1) -> MMA(kt) -> cvt/STS(kt+1) -> syncthreads
// SMEM fragment-order with XOR(kstep) swizzle -> all LDS/STS conflict-free.
// Dynamic SMEM 64KB: As[2] 2x16KB + Bs[2] 2x16KB.
// EPI: 0 = plain C write, 1 = QKV scatter to [B,H,S,3E]
template <int EPI>
__global__ void __launch_bounds__(512, 1) gemm_tc(GemmParams p)
{
    extern __shared__ uint32_t smem[];
    uint32_t* AsBuf[2] = { smem, smem + 4096 };
    uint32_t* BsBuf[2] = { smem + 8192, smem + 12288 };

    const int tid = threadIdx.x;
    const int lane = tid & 31;
    const int wid = tid >> 5;
    const int warp_m = wid & 3;   // 0..3
    const int warp_n = wid >> 2;  // 0..3

    const int bn = blockIdx.x;
    const int bm = blockIdx.y;
    const int z  = blockIdx.z;

    const float* A = p.A + (size_t)z * p.strideAz + (size_t)bm * 128 * p.lda;
    const float* Bp = p.B + (size_t)z * p.strideBz + (size_t)bn * 128 * p.ldb;

    // A loader: permute low-5 bits of row group so each warp's STS covers all banks.
    const int gA = tid >> 3;          // 0..63
    const int col4 = tid & 7;
    const int g5 = gA & 31;
    const int rowpA = (((g5 & 1) << 3) | ((g5 >> 1) & 1) | (((g5 >> 2) & 1) << 1)
                    | (((g5 >> 3) & 1) << 2) | (g5 & 16)) | (gA & 32);
    const int kstepL = col4 >> 1;     // k8 step of this thread's float4
    const int chi    = col4 & 1;      // k-half within 8
    const int rowB   = tid >> 3;      // B n-local row (t adds 64)

    float acc[2][4][4];
    #pragma unroll
    for (int i = 0; i < 2; i++)
        #pragma unroll
        for (int j = 0; j < 4; j++)
            #pragma unroll
            for (int r = 0; r < 4; r++) acc[i][j][r] = 0.f;

    float4 aR[2], bR[2];

    auto loadTile = [&](int k0) {
        #pragma unroll
        for (int t = 0; t < 2; t++) {
            aR[t] = *(const float4*)(A + (size_t)(rowpA + 64 * t) * p.lda + k0 + col4 * 4);
            bR[t] = *(const float4*)(Bp + (size_t)(rowB + 64 * t) * p.ldb + k0 + col4 * 4);
        }
    };

    auto storeTile = [&](uint32_t* as, uint32_t* bs) {
        #pragma unroll
        for (int t = 0; t < 2; t++) {
            const int row = rowpA + 64 * t;
            const int mtile = row >> 4;
            const int m8 = row & 7;
            const int reg = ((row >> 3) & 1) + 2 * chi;
            const uint32_t base = (uint32_t)(kstepL * 8 + mtile) * 128 + (m8 >> 1) * 32 + reg;
            float c[4] = {aR[t].x, aR[t].y, aR[t].z, aR[t].w};
            #pragma unroll
            for (int jj = 0; jj < 4; jj++) {
                const int lan = m8 * 4 + jj;
                as[base + (((lan & 7) ^ kstepL) << 2)] = f2tf32(c[jj]);
            }
        }
        #pragma unroll
        for (int t = 0; t < 2; t++) {
            const int row = rowB + 64 * t;
            const int ntile = row >> 3;
            const int n8 = row & 7;
            const uint32_t base = (uint32_t)(kstepL * 16 + ntile) * 64 + (n8 >> 2) * 32 + chi;
            float c[4] = {bR[t].x, bR[t].y, bR[t].z, bR[t].w};
            #pragma unroll
            for (int jj = 0; jj < 4; jj++) {
                const int lan = n8 * 4 + jj;
                bs[base + (((lan & 15) ^ kstepL) << 1)] = f2tf32(c[jj]);
            }
        }
    };

    auto compute = [&](const uint32_t* as, const uint32_t* bs) {
        #pragma unroll
        for (int ks = 0; ks < 4; ks++) {
            uint32_t af[2][4];
            uint32_t bf[4][2];
            #pragma unroll
            for (int mt = 0; mt < 2; mt++) {
                const int frag = ks * 8 + warp_m * 2 + mt;
                uint4 v = *(const uint4*)&as[frag * 128 + (lane >> 3) * 32 +
                                             (((lane & 7) ^ ks) << 2)];
                af[mt][0] = v.x; af[mt][1] = v.y; af[mt][2] = v.z; af[mt][3] = v.w;
            }
            #pragma unroll
            for (int nt = 0; nt < 4; nt++) {
                const int frag = ks * 16 + warp_n * 4 + nt;
                uint2 v = *(const uint2*)&bs[frag * 64 + (lane >> 4) * 32 +
                                             (((lane & 15) ^ ks) << 1)];
                bf[nt][0] = v.x; bf[nt][1] = v.y;
            }
            #pragma unroll
            for (int mt = 0; mt < 2; mt++)
                #pragma unroll
                for (int nt = 0; nt < 4; nt++)
                    mma_tf32(acc[mt][nt], af[mt], bf[nt]);
        }
    };

    // Prologue: tile 0 into buffer 0
    loadTile(0);
    storeTile(AsBuf[0], BsBuf[0]);
    __syncthreads();

    const int nIter = p.K >> 5;
    for (int kt = 0; kt < nIter; kt++) {
        const int buf = kt & 1;
        if (kt + 1 < nIter) loadTile((kt + 1) << 5);   // LDGs fly over the MMAs
        compute(AsBuf[buf], BsBuf[buf]);
        if (kt + 1 < nIter) storeTile(AsBuf[buf ^ 1], BsBuf[buf ^ 1]);
        __syncthreads();
    }

    // ---- Epilogue ----
    const size_t coff = (size_t)(z / p.divH) * p.strideCb +
                        (size_t)(z % p.divH) * p.strideCh;
    const int r  = lane >> 2;
    const int c2 = (lane & 3) * 2;

    #pragma unroll
    for (int mt = 0; mt < 2; mt++) {
        #pragma unroll
        for (int nt = 0; nt < 4; nt++) {
            const int n = bn * 128 + warp_n * 32 + nt * 8 + c2;
            float b0 = 0.f, b1 = 0.f;
            if (p.bias) {
                float2 bb = *(const float2*)&p.bias[n];
                b0 = bb.x; b1 = bb.y;
            }
            #pragma unroll
            for (int half = 0; half < 2; half++) {
                const int m = bm * 128 + warp_m * 32 + mt * 16 + r + half * 8;
                const float v0 = acc[mt][nt][half * 2 + 0] * p.alpha + b0;
                const float v1 = acc[mt][nt][half * 2 + 1] * p.alpha + b1;
                if (EPI == 1) {
                    const int b = m >> 10;
                    const int s = m & 1023;
                    const int h = n / F3;
                    const int f = n - h * F3;
                    *(float2*)&g_qkv[(((size_t)(b * Hn + h)) * Sn + s) * F3 + f] =
                        make_float2(v0, v1);
                } else {
                    *(float2*)&p.C[coff + (size_t)m * p.ldc + n] = make_float2(v0, v1);
                }
            }
        }
    }
}

// Transpose V slab of qkv: vT[bh, e, s] = qkv[bh, s, 2E + e]
__global__ void __launch_bounds__(256) transpose_v()
{
    __shared__ float tile[32][33];
    const int bh = blockIdx.z;
    const int s0 = blockIdx.x * 32;
    const int e0 = blockIdx.y * 32;
    const int tx = threadIdx.x;   // 0..31
    const int ty = threadIdx.y;   // 0..7
    const float* src = g_qkv + ((size_t)bh * Sn) * F3 + 2 * En;
    float* dst = g_vT + ((size_t)bh * En) * Sn;

    #pragma unroll
    for (int j = 0; j < 4; j++)
        tile[ty + 8 * j][tx] = src[(size_t)(s0 + ty + 8 * j) * F3 + e0 + tx];
    __syncthreads();
    #pragma unroll
    for (int j = 0; j < 4; j++)
        dst[(size_t)(e0 + ty + 8 * j) * Sn + s0 + tx] = tile[tx][ty + 8 * j];
}

// Softmax over rows of g_scores: one block (256 thr) per 1024-element row.
__global__ void __launch_bounds__(256) softmax_kernel(float* sc)
{
    float* row = sc + (size_t)blockIdx.x * Sn;
    const int tid = threadIdx.x;
    const int lane = tid & 31;
    const int wid = tid >> 5;
    __shared__ float red[8];

    float4 v = ((const float4*)row)[tid];
    float m = fmaxf(fmaxf(v.x, v.y), fmaxf(v.z, v.w));
    #pragma unroll
    for (int o = 16; o; o >>= 1) m = fmaxf(m, __shfl_xor_sync(~0u, m, o));
    if (lane == 0) red[wid] = m;
    __syncthreads();
    float bm = red[0];
    #pragma unroll
    for (int i = 1; i < 8; i++) bm = fmaxf(bm, red[i]);
    __syncthreads();

    float4 e;
    e.x = __expf(v.x - bm);
    e.y = __expf(v.y - bm);
    e.z = __expf(v.z - bm);
    e.w = __expf(v.w - bm);
    float s = e.x + e.y + e.z + e.w;
    #pragma unroll
    for (int o = 16; o; o >>= 1) s += __shfl_xor_sync(~0u, s, o);
    if (lane == 0) red[wid] = s;
    __syncthreads();
    float bs = red[0];
    #pragma unroll
    for (int i = 1; i < 8; i++) bs += red[i];
    const float rdiv = __frcp_rn(bs);

    e.x *= rdiv; e.y *= rdiv; e.z *= rdiv; e.w *= rdiv;
    ((float4*)row)[tid] = e;
}

#define GEMM_SMEM 65536

extern "C" void kernel_launch(void* const* d_in, const int* in_sizes, int n_in,
                              void* d_out, int out_size)
{
    const float* x     = (const float*)d_in[0];  // [B,S,E]
    const float* qkv_w = (const float*)d_in[1];  // [H,3E,E]
    const float* qkv_b = (const float*)d_in[2];  // [H,3E]
    const float* out_w = (const float*)d_in[3];  // [E,H*E]
    const float* out_b = (const float*)d_in[4];  // [E]
    float* out = (float*)d_out;                  // [B,S,E]

    float *qkv, *scores, *vT, *concat;
    cudaGetSymbolAddress((void**)&qkv,    g_qkv);
    cudaGetSymbolAddress((void**)&scores, g_scores);
    cudaGetSymbolAddress((void**)&vT,     g_vT);
    cudaGetSymbolAddress((void**)&concat, g_concat);

    cudaFuncSetAttribute(gemm_tc<0>, cudaFuncAttributeMaxDynamicSharedMemorySize, GEMM_SMEM);
    cudaFuncSetAttribute(gemm_tc<1>, cudaFuncAttributeMaxDynamicSharedMemorySize, GEMM_SMEM);

    // 1) QKV projection: [8192,768] x [27648,768]^T -> scatter [B,H,S,3E], +bias
    {
        GemmParams p = {};
        p.A = x; p.B = qkv_w; p.C = qkv;
        p.K = En; p.lda = En; p.ldb = En; p.ldc = 0;
        p.strideAz = 0; p.strideBz = 0;
        p.strideCb = 0; p.strideCh = 0; p.divH = 1;
        p.bias = qkv_b; p.alpha = 1.0f;
        gemm_tc<1><<<dim3(NQKV / 128, (Bn * Sn) / 128, 1), 512, GEMM_SMEM>>>(p);
    }

    // 1b) Transpose V slab -> vT [B*H, E, S]
    transpose_v<<<dim3(Sn / 32, En / 32, Bn * Hn), dim3(32, 8)>>>();

    // 2) Scores: per (b,h): Q[1024,768] x K[1024,768]^T * scale
    {
        GemmParams p = {};
        p.A = qkv; p.B = qkv + En; p.C = scores;
        p.K = En; p.lda = F3; p.ldb = F3; p.ldc = Sn;
        p.strideAz = (long long)Sn * F3;
        p.strideBz = (long long)Sn * F3;
        p.strideCb = (long long)Sn * Sn; p.strideCh = 0; p.divH = 1;
        p.bias = nullptr; p.alpha = 0.036084391824351615f; // 1/sqrt(768)
        gemm_tc<0><<<dim3(Sn / 128, Sn / 128, Bn * Hn), 512, GEMM_SMEM>>>(p);
    }

    // 3) Softmax rows
    softmax_kernel<<<Bn * Hn * Sn, 256>>>(scores);

    // 4) AV: per (b,h): P[1024,1024] x vT[768,1024]^T -> concat [B,S,H,E]
    {
        GemmParams p = {};
        p.A = scores; p.B = vT; p.C = concat;
        p.K = Sn; p.lda = Sn; p.ldb = Sn; p.ldc = HE;
        p.strideAz = (long long)Sn * Sn;
        p.strideBz = (long long)En * Sn;
        p.strideCb = (long long)Sn * Hn * En;
        p.strideCh = En;
        p.divH = Hn;
        p.bias = nullptr; p.alpha = 1.0f;
        gemm_tc<0><<<dim3(En / 128, Sn / 128, Bn * Hn), 512, GEMM_SMEM>>>(p);
    }

    // 5) Output projection: [8192,9216] x [768,9216]^T + bias -> [8192,768]
    {
        GemmParams p = {};
        p.A = concat; p.B = out_w; p.C = out;
        p.K = HE; p.lda = HE; p.ldb = HE; p.ldc = En;
        p.strideAz = 0; p.strideBz = 0;
        p.strideCb = 0; p.strideCh = 0; p.divH = 1;
        p.bias = out_b; p.alpha = 1.0f;
        gemm_tc<0><<<dim3(En / 128, (Bn * Sn) / 128, 1), 512, GEMM_SMEM>>>(p);
    }
}

// round 8
// speedup vs baseline: 2.0694x; 1.9155x over previous
#include <cuda_runtime.h>
#include <stdint.h>

// Problem constants
#define Bn 8
#define Sn 1024
#define En 768
#define Hn 12
#define F3 2304          // 3*E
#define NQKV 27648       // H*3E
#define HE 9216          // H*E

// Scratch (allocation-free: __device__ globals)
__device__ float g_qkv[(size_t)Bn * Hn * Sn * F3];     // [B,H,S,3E]
__device__ float g_scores[(size_t)Bn * Hn * Sn * Sn];  // [B*H,S,S]
__device__ float g_vT[(size_t)Bn * Hn * En * Sn];      // [B*H,E,S]
__device__ float g_concat[(size_t)Bn * Sn * Hn * En];  // [B,S,H,E]

struct GemmParams {
    const float* A;   // [M,K] K-major, row stride lda
    const float* B;   // [N,K] K-major, row stride ldb
    float* C;
    int K;
    int lda, ldb, ldc;
    long long strideAz, strideBz;
    long long strideCb, strideCh;
    int divH;
    const float* bias;
    float alpha;
};

__device__ __forceinline__ uint32_t f2tf32(float x) {
    uint32_t r;
    asm("cvt.rna.tf32.f32 %0, %1;" : "=r"(r) : "f"(x));
    return r;
}

__device__ __forceinline__ void mma_tf32(float* d, const uint32_t* a, const uint32_t* b) {
    asm volatile(
        "mma.sync.aligned.m16n8k8.row.col.f32.tf32.tf32.f32 "
        "{%0,%1,%2,%3}, {%4,%5,%6,%7}, {%8,%9}, {%0,%1,%2,%3};"
        : "+f"(d[0]), "+f"(d[1]), "+f"(d[2]), "+f"(d[3])
        : "r"(a[0]), "r"(a[1]), "r"(a[2]), "r"(a[3]), "r"(b[0]), "r"(b[1]));
}

__device__ __forceinline__ uint32_t smem_u32_g(const void* p) {
    uint32_t a;
    asm("{ .reg .u64 t; cvta.to.shared.u64 t, %1; cvt.u32.u64 %0, t; }"
        : "=r"(a) : "l"(p));
    return a;
}

#if defined(__CUDA_ARCH_FEAT_SM103_ALL)
// ---------- sm_103a-only PTX helpers (tcgen05) ----------
__device__ __forceinline__ uint32_t elect_one() {
    uint32_t p;
    asm volatile(
        "{\n\t.reg .pred p;\n\telect.sync _|p, 0xFFFFFFFF;\n\t"
        "selp.b32 %0, 1, 0, p;\n\t}" : "=r"(p));
    return p;
}

#define TCGEN05_ALLOC(a, n) \
    asm volatile("tcgen05.alloc.cta_group::1.sync.aligned.shared::cta.b32 [%0], %1;" \
                 :: "r"(a), "r"(n) : "memory")
#define TCGEN05_DEALLOC(t, n) \
    asm volatile("tcgen05.dealloc.cta_group::1.sync.aligned.b32 %0, %1;" :: "r"(t), "r"(n))
#define TCGEN05_RELINQ() \
    asm volatile("tcgen05.relinquish_alloc_permit.cta_group::1.sync.aligned;")
#define TCGEN05_COMMIT(m) \
    asm volatile("tcgen05.commit.cta_group::1.mbarrier::arrive::one.shared::cluster.b64 [%0];" \
                 :: "r"(m) : "memory")
#define MBARRIER_INIT(m, c) \
    asm volatile("mbarrier.init.shared.b64 [%0], %1;" :: "r"(m), "r"(c) : "memory")
#define MBARRIER_INVAL(m) \
    asm volatile("mbarrier.inval.shared.b64 [%0];" :: "r"(m) : "memory")
#define TCGEN05_FENCE_AFTER()  asm volatile("tcgen05.fence::after_thread_sync;" ::: "memory")
#define TCGEN05_FENCE_BEFORE() asm volatile("tcgen05.fence::before_thread_sync;" ::: "memory")
#define TCGEN05_WAIT_LD()      asm volatile("tcgen05.wait::ld.sync.aligned;" ::: "memory")
#define FENCE_ASYNC()          asm volatile("fence.proxy.async.shared::cta;" ::: "memory")

#define MBARRIER_WAIT_PARITY(mbar_smem_addr, phase_parity) do { \
    uint32_t _mbar = (uint32_t)(mbar_smem_addr); \
    uint32_t _parity = (uint32_t)(phase_parity); \
    uint32_t _done; \
    asm volatile( \
        "{\n\t.reg .pred p;\n\t" \
        "mbarrier.try_wait.parity.acquire.cta.shared::cta.b64 p, [%1], %2;\n\t" \
        "selp.b32 %0, 1, 0, p;\n\t}" \
        : "=r"(_done) : "r"(_mbar), "r"(_parity) : "memory"); \
    if (!_done) { \
        asm volatile( \
            "{\n\t.reg .pred P1;\n\t" \
            "WAIT_LOOP_%=:\n\t" \
            "mbarrier.try_wait.parity.acquire.cta.shared::cta.b64 P1, [%0], %1, 0x989680;\n\t" \
            "@P1 bra.uni WAIT_DONE_%=;\n\t" \
            "bra.uni WAIT_LOOP_%=;\n\t" \
            "WAIT_DONE_%=:\n\t}" \
            :: "r"(_mbar), "r"(_parity) : "memory"); \
    } \
} while (0)

#define TCGEN05_LD_32X32B_X32(r, tmem_addr) \
    asm volatile( \
        "tcgen05.ld.sync.aligned.32x32b.x32.b32 " \
        "{%0, %1, %2, %3, %4, %5, %6, %7, " \
        " %8, %9, %10, %11, %12, %13, %14, %15, " \
        " %16, %17, %18, %19, %20, %21, %22, %23, " \
        " %24, %25, %26, %27, %28, %29, %30, %31}, [%32];" \
        : "=r"((r)[0]),  "=r"((r)[1]),  "=r"((r)[2]),  "=r"((r)[3]), \
          "=r"((r)[4]),  "=r"((r)[5]),  "=r"((r)[6]),  "=r"((r)[7]), \
          "=r"((r)[8]),  "=r"((r)[9]),  "=r"((r)[10]), "=r"((r)[11]), \
          "=r"((r)[12]), "=r"((r)[13]), "=r"((r)[14]), "=r"((r)[15]), \
          "=r"((r)[16]), "=r"((r)[17]), "=r"((r)[18]), "=r"((r)[19]), \
          "=r"((r)[20]), "=r"((r)[21]), "=r"((r)[22]), "=r"((r)[23]), \
          "=r"((r)[24]), "=r"((r)[25]), "=r"((r)[26]), "=r"((r)[27]), \
          "=r"((r)[28]), "=r"((r)[29]), "=r"((r)[30]), "=r"((r)[31]) \
        : "r"(tmem_addr))

// SW128 K-major SMEM descriptor (128B rows): layout=SW128, version=1, SBO=64, LBO=1
static __device__ __forceinline__ uint64_t mk_desc(uint32_t addr) {
    const uint64_t base = (2ULL << 61) | (1ULL << 46) | (64ULL << 32) | (1ULL << 16);
    return base | ((uint64_t)(addr >> 4) & 0x3FFF);
}

// idesc kind::tf32: dtype F32=1 @bit4, atype=TF32=2 @bit7, btype=TF32=2 @bit10,
// N/8 @bit17, M/16 @bit24   (M=128, N=128)
#define IDESC_TF32 ((1u << 4) | (2u << 7) | (2u << 10) | (16u << 17) | (8u << 24))

__device__ __forceinline__ void mma_tf32_ss(uint32_t d_tmem, uint64_t ad, uint64_t bd,
                                            uint32_t en) {
    asm volatile(
        "{\n\t.reg .pred pq;\n\tsetp.ne.u32 pq, %5, 0;\n\t"
        "tcgen05.mma.cta_group::1.kind::tf32 [%0], %1, %2, %3, {%4, %4, %4, %4}, pq;\n\t}"
        :: "r"(d_tmem), "l"(ad), "l"(bd), "r"(IDESC_TF32), "r"(0u), "r"(en)
        : "memory");
}
#endif  // __CUDA_ARCH_FEAT_SM103_ALL

// ---------- GEMM: A[M,K] x B[N,K]^T, tile 128x128, 256 threads ----------
// sm_103a pass: tcgen05 SS pipeline, tiles runtime-aligned to 1024B for SW128.
// other passes: mma.sync tf32 fallback (R3-proven swizzled fragment layout).
// EPI: 0 = plain C write, 1 = QKV scatter to [B,H,S,3E]
template <int EPI>
__global__ void __launch_bounds__(256) gemm_tc5(GemmParams p)
{
    extern __shared__ __align__(16) float smem_raw[];
    // Align tile base to 1024 bytes (SW128 swizzle contract).
    const uint32_t raw_u  = smem_u32_g(smem_raw);
    const uint32_t smem_u = (raw_u + 1023u) & ~1023u;
    float* smem = (float*)((char*)smem_raw + (smem_u - raw_u));

    const int tid = threadIdx.x;
    const int lane = tid & 31;
    const int wid = tid >> 5;
    const int bn = blockIdx.x, bm = blockIdx.y, z = blockIdx.z;

    const float* A  = p.A + (size_t)z * p.strideAz + (size_t)bm * 128 * p.lda;
    const float* Bp = p.B + (size_t)z * p.strideBz + (size_t)bn * 128 * p.ldb;
    const size_t coff = (size_t)(z / p.divH) * p.strideCb +
                        (size_t)(z % p.divH) * p.strideCh;

#if defined(__CUDA_ARCH_FEAT_SM103_ALL)
    // ================= tcgen05 path =================
    __shared__ uint32_t s_tmem;
    __shared__ __align__(8) unsigned long long s_mbar[2];

    const uint32_t mbar_u = smem_u32_g(s_mbar);

    if (wid == 0) {
        TCGEN05_ALLOC(smem_u32_g(&s_tmem), 128);
        TCGEN05_RELINQ();
    }
    if (tid == 0) {
        MBARRIER_INIT(mbar_u, 1);
        MBARRIER_INIT(mbar_u + 8, 1);
    }
    __syncthreads();
    const uint32_t tmem = s_tmem;

    auto loadTile = [&](int k0, int buf) {
        float* sa = smem + buf * 8192;
        float* sb = sa + 4096;
        #pragma unroll
        for (int i = 0; i < 4; i++) {
            const int idx = tid + 256 * i;
            const int row = idx >> 3;
            const int c4  = idx & 7;
            float4 av = *(const float4*)(A  + (size_t)row * p.lda + k0 + c4 * 4);
            float4 bv = *(const float4*)(Bp + (size_t)row * p.ldb + k0 + c4 * 4);
            uint32_t off = (uint32_t)(row * 128 + c4 * 16);
            uint32_t sw  = off ^ ((off >> 3) & 0x70);
            uint4 at = make_uint4(f2tf32(av.x), f2tf32(av.y), f2tf32(av.z), f2tf32(av.w));
            uint4 bt = make_uint4(f2tf32(bv.x), f2tf32(bv.y), f2tf32(bv.z), f2tf32(bv.w));
            *(uint4*)((char*)sa + sw) = at;
            *(uint4*)((char*)sb + sw) = bt;
        }
        FENCE_ASYNC();
    };

    loadTile(0, 0);
    __syncthreads();

    int ph0 = 0, ph1 = 0;
    const int nIter = p.K >> 5;   // 24 / 32 / 288 -> always even
    for (int kt = 0; kt < nIter; kt++) {
        const int buf = kt & 1;
        if (wid == 0) {
            if (elect_one()) {
                const uint64_t ad = mk_desc(smem_u + buf * 32768u);
                const uint64_t bd = mk_desc(smem_u + buf * 32768u + 16384u);
                #pragma unroll
                for (int ks = 0; ks < 4; ks++)
                    mma_tf32_ss(tmem, ad + ks * 2, bd + ks * 2,
                                (kt > 0 || ks > 0) ? 1u : 0u);
                TCGEN05_COMMIT(mbar_u + buf * 8);
            }
        }
        if (kt + 1 < nIter) {
            if (kt >= 1) {
                if ((buf ^ 1) == 0) { MBARRIER_WAIT_PARITY(mbar_u,     ph0); ph0 ^= 1; }
                else               { MBARRIER_WAIT_PARITY(mbar_u + 8, ph1); ph1 ^= 1; }
            }
            loadTile((kt + 1) << 5, buf ^ 1);
        }
        __syncthreads();
    }

    MBARRIER_WAIT_PARITY(mbar_u,     ph0);
    MBARRIER_WAIT_PARITY(mbar_u + 8, ph1);
    TCGEN05_FENCE_AFTER();

    // Epilogue: warp wid -> rows (wid&3)*32+lane, cols [(wid>>2)*64, +64)
    uint32_t r0[32], r1[32];
    const uint32_t cb = (uint32_t)(wid >> 2) * 64;
    TCGEN05_LD_32X32B_X32(r0, tmem + cb);
    TCGEN05_LD_32X32B_X32(r1, tmem + cb + 32);
    TCGEN05_WAIT_LD();
    TCGEN05_FENCE_BEFORE();

    const int m  = bm * 128 + (wid & 3) * 32 + lane;
    const int n0 = bn * 128 + (int)cb;

    float* dst;
    if (EPI == 1) {
        const int b = m >> 10, s = m & 1023;
        const int h = n0 / F3, f = n0 - h * F3;
        dst = &g_qkv[(((size_t)(b * Hn + h)) * Sn + s) * F3 + f];
    } else {
        dst = &p.C[coff + (size_t)m * p.ldc + n0];
    }
    #pragma unroll
    for (int j = 0; j < 64; j += 4) {
        const uint32_t* rr = (j < 32) ? r0 : r1;
        const int jj = j & 31;
        float4 v;
        v.x = __uint_as_float(rr[jj + 0]) * p.alpha;
        v.y = __uint_as_float(rr[jj + 1]) * p.alpha;
        v.z = __uint_as_float(rr[jj + 2]) * p.alpha;
        v.w = __uint_as_float(rr[jj + 3]) * p.alpha;
        if (p.bias) {
            float4 bb = *(const float4*)&p.bias[n0 + j];
            v.x += bb.x; v.y += bb.y; v.z += bb.z; v.w += bb.w;
        }
        *(float4*)&dst[j] = v;
    }

    __syncthreads();
    if (tid == 0) { MBARRIER_INVAL(mbar_u); MBARRIER_INVAL(mbar_u + 8); }
    __syncthreads();
    if (wid == 0) TCGEN05_DEALLOC(tmem, 128);

#else
    // ================= mma.sync fallback (R3-proven) =================
    uint32_t* As = (uint32_t*)smem;          // 4096 words
    uint32_t* Bs = (uint32_t*)smem + 4096;   // 4096 words

    const int warp_m = wid & 1;   // 0..1
    const int warp_n = wid >> 1;  // 0..3

    const int gA = tid >> 3;
    const int col4 = tid & 7;
    const int rowpA = ((gA & 1) << 3) | ((gA >> 1) & 1) | (((gA >> 2) & 1) << 1)
                    | (((gA >> 3) & 1) << 2) | (gA & 16);
    const int kstepL = col4 >> 1;
    const int chi    = col4 & 1;

    float acc[4][4][4];
    #pragma unroll
    for (int i = 0; i < 4; i++)
        #pragma unroll
        for (int j = 0; j < 4; j++)
            #pragma unroll
            for (int r = 0; r < 4; r++) acc[i][j][r] = 0.f;

    for (int k0 = 0; k0 < p.K; k0 += 32) {
        #pragma unroll
        for (int t = 0; t < 4; t++) {
            const int row = rowpA + 32 * t;
            float4 v = *(const float4*)(A + (size_t)row * p.lda + k0 + col4 * 4);
            const int mtile = row >> 4;
            const int m8 = row & 7;
            const int reg = ((row >> 3) & 1) + 2 * chi;
            const uint32_t base = (uint32_t)(kstepL * 8 + mtile) * 128 + (m8 >> 1) * 32 + reg;
            float c[4] = {v.x, v.y, v.z, v.w};
            #pragma unroll
            for (int jj = 0; jj < 4; jj++) {
                const int lan = m8 * 4 + jj;
                As[base + (((lan & 7) ^ kstepL) << 2)] = f2tf32(c[jj]);
            }
        }
        #pragma unroll
        for (int t = 0; t < 4; t++) {
            const int idx = tid + 256 * t;
            const int row = idx >> 3;
            float4 v = *(const float4*)(Bp + (size_t)row * p.ldb + k0 + col4 * 4);
            const int ntile = row >> 3;
            const int n8 = row & 7;
            const uint32_t base = (uint32_t)(kstepL * 16 + ntile) * 64 + (n8 >> 2) * 32 + chi;
            float c[4] = {v.x, v.y, v.z, v.w};
            #pragma unroll
            for (int jj = 0; jj < 4; jj++) {
                const int lan = n8 * 4 + jj;
                Bs[base + (((lan & 15) ^ kstepL) << 1)] = f2tf32(c[jj]);
            }
        }
        __syncthreads();

        #pragma unroll
        for (int ks = 0; ks < 4; ks++) {
            uint32_t af[4][4];
            uint32_t bf[4][2];
            #pragma unroll
            for (int mt = 0; mt < 4; mt++) {
                const int frag = ks * 8 + warp_m * 4 + mt;
                uint4 v = *(const uint4*)&As[frag * 128 + (lane >> 3) * 32 +
                                             (((lane & 7) ^ ks) << 2)];
                af[mt][0] = v.x; af[mt][1] = v.y; af[mt][2] = v.z; af[mt][3] = v.w;
            }
            #pragma unroll
            for (int nt = 0; nt < 4; nt++) {
                const int frag = ks * 16 + warp_n * 4 + nt;
                uint2 v = *(const uint2*)&Bs[frag * 64 + (lane >> 4) * 32 +
                                             (((lane & 15) ^ ks) << 1)];
                bf[nt][0] = v.x; bf[nt][1] = v.y;
            }
            #pragma unroll
            for (int mt = 0; mt < 4; mt++)
                #pragma unroll
                for (int nt = 0; nt < 4; nt++)
                    mma_tf32(acc[mt][nt], af[mt], bf[nt]);
        }
        __syncthreads();
    }

    const int r  = lane >> 2;
    const int c2 = (lane & 3) * 2;

    #pragma unroll
    for (int mt = 0; mt < 4; mt++) {
        #pragma unroll
        for (int nt = 0; nt < 4; nt++) {
            const int n = bn * 128 + warp_n * 32 + nt * 8 + c2;
            float b0 = 0.f, b1 = 0.f;
            if (p.bias) {
                float2 bb = *(const float2*)&p.bias[n];
                b0 = bb.x; b1 = bb.y;
            }
            #pragma unroll
            for (int half = 0; half < 2; half++) {
                const int m = bm * 128 + warp_m * 64 + mt * 16 + r + half * 8;
                const float v0 = acc[mt][nt][half * 2 + 0] * p.alpha + b0;
                const float v1 = acc[mt][nt][half * 2 + 1] * p.alpha + b1;
                if (EPI == 1) {
                    const int b = m >> 10;
                    const int s = m & 1023;
                    const int h = n / F3;
                    const int f = n - h * F3;
                    *(float2*)&g_qkv[(((size_t)(b * Hn + h)) * Sn + s) * F3 + f] =
                        make_float2(v0, v1);
                } else {
                    *(float2*)&p.C[coff + (size_t)m * p.ldc + n] = make_float2(v0, v1);
                }
            }
        }
    }
#endif
}

// Transpose V slab of qkv: vT[bh, e, s] = qkv[bh, s, 2E + e]
__global__ void __launch_bounds__(256) transpose_v()
{
    __shared__ float tile[32][33];
    const int bh = blockIdx.z;
    const int s0 = blockIdx.x * 32;
    const int e0 = blockIdx.y * 32;
    const int tx = threadIdx.x;
    const int ty = threadIdx.y;
    const float* src = g_qkv + ((size_t)bh * Sn) * F3 + 2 * En;
    float* dst = g_vT + ((size_t)bh * En) * Sn;

    #pragma unroll
    for (int j = 0; j < 4; j++)
        tile[ty + 8 * j][tx] = src[(size_t)(s0 + ty + 8 * j) * F3 + e0 + tx];
    __syncthreads();
    #pragma unroll
    for (int j = 0; j < 4; j++)
        dst[(size_t)(e0 + ty + 8 * j) * Sn + s0 + tx] = tile[tx][ty + 8 * j];
}

// Softmax over rows of g_scores: one block (256 thr) per 1024-element row.
__global__ void __launch_bounds__(256) softmax_kernel(float* sc)
{
    float* row = sc + (size_t)blockIdx.x * Sn;
    const int tid = threadIdx.x;
    const int lane = tid & 31;
    const int wid = tid >> 5;
    __shared__ float red[8];

    float4 v = ((const float4*)row)[tid];
    float m = fmaxf(fmaxf(v.x, v.y), fmaxf(v.z, v.w));
    #pragma unroll
    for (int o = 16; o; o >>= 1) m = fmaxf(m, __shfl_xor_sync(~0u, m, o));
    if (lane == 0) red[wid] = m;
    __syncthreads();
    float bm = red[0];
    #pragma unroll
    for (int i = 1; i < 8; i++) bm = fmaxf(bm, red[i]);
    __syncthreads();

    float4 e;
    e.x = __expf(v.x - bm);
    e.y = __expf(v.y - bm);
    e.z = __expf(v.z - bm);
    e.w = __expf(v.w - bm);
    float s = e.x + e.y + e.z + e.w;
    #pragma unroll
    for (int o = 16; o; o >>= 1) s += __shfl_xor_sync(~0u, s, o);
    if (lane == 0) red[wid] = s;
    __syncthreads();
    float bs = red[0];
    #pragma unroll
    for (int i = 1; i < 8; i++) bs += red[i];
    const float rdiv = __frcp_rn(bs);

    e.x *= rdiv; e.y *= rdiv; e.z *= rdiv; e.w *= rdiv;
    ((float4*)row)[tid] = e;
}

#define GEMM_SMEM 66560   // 64KB tiles + 1KB alignment slack

extern "C" void kernel_launch(void* const* d_in, const int* in_sizes, int n_in,
                              void* d_out, int out_size)
{
    const float* x     = (const float*)d_in[0];  // [B,S,E]
    const float* qkv_w = (const float*)d_in[1];  // [H,3E,E]
    const float* qkv_b = (const float*)d_in[2];  // [H,3E]
    const float* out_w = (const float*)d_in[3];  // [E,H*E]
    const float* out_b = (const float*)d_in[4];  // [E]
    float* out = (float*)d_out;                  // [B,S,E]

    float *qkv, *scores, *vT, *concat;
    cudaGetSymbolAddress((void**)&qkv,    g_qkv);
    cudaGetSymbolAddress((void**)&scores, g_scores);
    cudaGetSymbolAddress((void**)&vT,     g_vT);
    cudaGetSymbolAddress((void**)&concat, g_concat);

    cudaFuncSetAttribute(gemm_tc5<0>, cudaFuncAttributeMaxDynamicSharedMemorySize, GEMM_SMEM);
    cudaFuncSetAttribute(gemm_tc5<1>, cudaFuncAttributeMaxDynamicSharedMemorySize, GEMM_SMEM);

    // 1) QKV projection: [8192,768] x [27648,768]^T -> scatter [B,H,S,3E], +bias
    {
        GemmParams p = {};
        p.A = x; p.B = qkv_w; p.C = qkv;
        p.K = En; p.lda = En; p.ldb = En; p.ldc = 0;
        p.strideAz = 0; p.strideBz = 0;
        p.strideCb = 0; p.strideCh = 0; p.divH = 1;
        p.bias = qkv_b; p.alpha = 1.0f;
        gemm_tc5<1><<<dim3(NQKV / 128, (Bn * Sn) / 128, 1), 256, GEMM_SMEM>>>(p);
    }

    // 1b) Transpose V slab -> vT [B*H, E, S]
    transpose_v<<<dim3(Sn / 32, En / 32, Bn * Hn), dim3(32, 8)>>>();

    // 2) Scores: per (b,h): Q[1024,768] x K[1024,768]^T * scale
    {
        GemmParams p = {};
        p.A = qkv; p.B = qkv + En; p.C = scores;
        p.K = En; p.lda = F3; p.ldb = F3; p.ldc = Sn;
        p.strideAz = (long long)Sn * F3;
        p.strideBz = (long long)Sn * F3;
        p.strideCb = (long long)Sn * Sn; p.strideCh = 0; p.divH = 1;
        p.bias = nullptr; p.alpha = 0.036084391824351615f; // 1/sqrt(768)
        gemm_tc5<0><<<dim3(Sn / 128, Sn / 128, Bn * Hn), 256, GEMM_SMEM>>>(p);
    }

    // 3) Softmax rows
    softmax_kernel<<<Bn * Hn * Sn, 256>>>(scores);

    // 4) AV: per (b,h): P[1024,1024] x vT[768,1024]^T -> concat [B,S,H,E]
    {
        GemmParams p = {};
        p.A = scores; p.B = vT; p.C = concat;
        p.K = Sn; p.lda = Sn; p.ldb = Sn; p.ldc = HE;
        p.strideAz = (long long)Sn * Sn;
        p.strideBz = (long long)En * Sn;
        p.strideCb = (long long)Sn * Hn * En;
        p.strideCh = En;
        p.divH = Hn;
        p.bias = nullptr; p.alpha = 1.0f;
        gemm_tc5<0><<<dim3(En / 128, Sn / 128, Bn * Hn), 256, GEMM_SMEM>>>(p);
    }

    // 5) Output projection: [8192,9216] x [768,9216]^T + bias -> [8192,768]
    {
        GemmParams p = {};
        p.A = concat; p.B = out_w; p.C = out;
        p.K = HE; p.lda = HE; p.ldb = HE; p.ldc = En;
        p.strideAz = 0; p.strideBz = 0;
        p.strideCb = 0; p.strideCh = 0; p.divH = 1;
        p.bias = out_b; p.alpha = 1.0f;
        gemm_tc5<0><<<dim3(En / 128, (Bn * Sn) / 128, 1), 256, GEMM_SMEM>>>(p);
    }
}

// round 9
// speedup vs baseline: 4.0175x; 1.9414x over previous
#include <cuda_runtime.h>
#include <cuda.h>
#include <stdint.h>

// Problem constants
#define Bn 8
#define Sn 1024
#define En 768
#define Hn 12
#define F3 2304          // 3*E
#define NQKV 27648       // H*3E
#define HE 9216          // H*E

// Scratch (allocation-free: __device__ globals)
__device__ float g_qkv[(size_t)Bn * Hn * Sn * F3];     // [B,H,S,3E] (tf32-rounded)
__device__ float g_scores[(size_t)Bn * Hn * Sn * Sn];  // [B*H,S,S]
__device__ float g_vT[(size_t)Bn * Hn * En * Sn];      // [B*H,E,S]  (tf32-rounded)
__device__ float g_concat[(size_t)Bn * Sn * Hn * En];  // [B,S,H,E]  (tf32-rounded)
__device__ float g_xr[(size_t)Bn * Sn * En];           // rounded x
__device__ float g_wqkvr[(size_t)NQKV * En];           // rounded qkv_w
__device__ float g_owr[(size_t)En * HE];               // rounded out_w

struct GemmParams {
    const float* A;   // [M,K] K-major (fallback only)
    const float* B;   // [N,K] K-major (fallback only)
    float* C;
    int K;
    int lda, ldb, ldc;
    long long strideAz, strideBz;
    long long strideCb, strideCh;
    int divH;
    const float* bias;
    float alpha;
};

__device__ __forceinline__ uint32_t f2tf32(float x) {
    uint32_t r;
    asm("cvt.rna.tf32.f32 %0, %1;" : "=r"(r) : "f"(x));
    return r;
}

__device__ __forceinline__ uint32_t smem_u32_g(const void* p) {
    uint32_t a;
    asm("{ .reg .u64 t; cvta.to.shared.u64 t, %1; cvt.u32.u64 %0, t; }"
        : "=r"(a) : "l"(p));
    return a;
}

#if defined(__CUDA_ARCH_FEAT_SM103_ALL)
// ---------- sm_103a-only helpers ----------
__device__ __forceinline__ uint32_t elect_one() {
    uint32_t p;
    asm volatile(
        "{\n\t.reg .pred p;\n\telect.sync _|p, 0xFFFFFFFF;\n\t"
        "selp.b32 %0, 1, 0, p;\n\t}" : "=r"(p));
    return p;
}

#define TCGEN05_ALLOC(a, n) \
    asm volatile("tcgen05.alloc.cta_group::1.sync.aligned.shared::cta.b32 [%0], %1;" \
                 :: "r"(a), "r"(n) : "memory")
#define TCGEN05_DEALLOC(t, n) \
    asm volatile("tcgen05.dealloc.cta_group::1.sync.aligned.b32 %0, %1;" :: "r"(t), "r"(n))
#define TCGEN05_RELINQ() \
    asm volatile("tcgen05.relinquish_alloc_permit.cta_group::1.sync.aligned;")
#define TCGEN05_COMMIT(m) \
    asm volatile("tcgen05.commit.cta_group::1.mbarrier::arrive::one.shared::cluster.b64 [%0];" \
                 :: "r"(m) : "memory")
#define MBARRIER_INIT(m, c) \
    asm volatile("mbarrier.init.shared.b64 [%0], %1;" :: "r"(m), "r"(c) : "memory")
#define MBARRIER_INVAL(m) \
    asm volatile("mbarrier.inval.shared.b64 [%0];" :: "r"(m) : "memory")
#define MBARRIER_EXPECT_TX(m, b) \
    asm volatile("mbarrier.arrive.expect_tx.shared.b64 _, [%0], %1;" \
                 :: "r"(m), "r"(b) : "memory")
#define TCGEN05_FENCE_AFTER()  asm volatile("tcgen05.fence::after_thread_sync;" ::: "memory")
#define TCGEN05_FENCE_BEFORE() asm volatile("tcgen05.fence::before_thread_sync;" ::: "memory")
#define TCGEN05_WAIT_LD()      asm volatile("tcgen05.wait::ld.sync.aligned;" ::: "memory")
#define FENCE_ASYNC()          asm volatile("fence.proxy.async.shared::cta;" ::: "memory")

#define TMA3D(sm, mapp, cx, cy, cz, mb) \
    asm volatile( \
        "cp.async.bulk.tensor.3d.shared::cta.global.tile.mbarrier::complete_tx::bytes " \
        "[%0], [%1, {%2, %3, %4}], [%5];" \
        :: "r"(sm), "l"(mapp), "r"(cx), "r"(cy), "r"(cz), "r"(mb) : "memory")

#define MBARRIER_WAIT_PARITY(mbar_smem_addr, phase_parity) do { \
    uint32_t _mbar = (uint32_t)(mbar_smem_addr); \
    uint32_t _parity = (uint32_t)(phase_parity); \
    uint32_t _done; \
    asm volatile( \
        "{\n\t.reg .pred p;\n\t" \
        "mbarrier.try_wait.parity.acquire.cta.shared::cta.b64 p, [%1], %2;\n\t" \
        "selp.b32 %0, 1, 0, p;\n\t}" \
        : "=r"(_done) : "r"(_mbar), "r"(_parity) : "memory"); \
    if (!_done) { \
        asm volatile( \
            "{\n\t.reg .pred P1;\n\t" \
            "WAIT_LOOP_%=:\n\t" \
            "mbarrier.try_wait.parity.acquire.cta.shared::cta.b64 P1, [%0], %1, 0x989680;\n\t" \
            "@P1 bra.uni WAIT_DONE_%=;\n\t" \
            "bra.uni WAIT_LOOP_%=;\n\t" \
            "WAIT_DONE_%=:\n\t}" \
            :: "r"(_mbar), "r"(_parity) : "memory"); \
    } \
} while (0)

#define TCGEN05_LD_32X32B_X32(r, tmem_addr) \
    asm volatile( \
        "tcgen05.ld.sync.aligned.32x32b.x32.b32 " \
        "{%0, %1, %2, %3, %4, %5, %6, %7, " \
        " %8, %9, %10, %11, %12, %13, %14, %15, " \
        " %16, %17, %18, %19, %20, %21, %22, %23, " \
        " %24, %25, %26, %27, %28, %29, %30, %31}, [%32];" \
        : "=r"((r)[0]),  "=r"((r)[1]),  "=r"((r)[2]),  "=r"((r)[3]), \
          "=r"((r)[4]),  "=r"((r)[5]),  "=r"((r)[6]),  "=r"((r)[7]), \
          "=r"((r)[8]),  "=r"((r)[9]),  "=r"((r)[10]), "=r"((r)[11]), \
          "=r"((r)[12]), "=r"((r)[13]), "=r"((r)[14]), "=r"((r)[15]), \
          "=r"((r)[16]), "=r"((r)[17]), "=r"((r)[18]), "=r"((r)[19]), \
          "=r"((r)[20]), "=r"((r)[21]), "=r"((r)[22]), "=r"((r)[23]), \
          "=r"((r)[24]), "=r"((r)[25]), "=r"((r)[26]), "=r"((r)[27]), \
          "=r"((r)[28]), "=r"((r)[29]), "=r"((r)[30]), "=r"((r)[31]) \
        : "r"(tmem_addr))

// SW128 K-major SMEM descriptor (128B rows): layout=SW128, version=1, SBO=64, LBO=1
static __device__ __forceinline__ uint64_t mk_desc(uint32_t addr) {
    const uint64_t base = (2ULL << 61) | (1ULL << 46) | (64ULL << 32) | (1ULL << 16);
    return base | ((uint64_t)(addr >> 4) & 0x3FFF);
}

// idesc kind::tf32: dtype F32=1 @bit4, atype=btype=TF32=2 @bits7/10,
// N/8 @bit17, M/16 @bit24   (M=128, N=256)
#define IDESC_TF32 ((1u << 4) | (2u << 7) | (2u << 10) | (32u << 17) | (8u << 24))

__device__ __forceinline__ void mma_tf32_ss(uint32_t d_tmem, uint64_t ad, uint64_t bd,
                                            uint32_t en) {
    asm volatile(
        "{\n\t.reg .pred pq;\n\tsetp.ne.u32 pq, %5, 0;\n\t"
        "tcgen05.mma.cta_group::1.kind::tf32 [%0], %1, %2, %3, {%4, %4, %4, %4}, pq;\n\t}"
        :: "r"(d_tmem), "l"(ad), "l"(bd), "r"(IDESC_TF32), "r"(0u), "r"(en)
        : "memory");
}
#endif  // __CUDA_ARCH_FEAT_SM103_ALL

// ---------- GEMM: A[M,K] x B[N,K]^T, tile 128x256, 256 threads ----------
// sm_103a: TMA-fed double-buffered tcgen05 SS pipeline; single elected driver
// thread issues TMA + MMA + mbarriers; all inputs pre-rounded to tf32 bits.
// EPI: 0 = plain C write, 1 = QKV scatter. ROUND: round stored values to tf32.
template <int EPI, int ROUND>
__global__ void __launch_bounds__(256, 2) gemm_tma(
    const __grid_constant__ CUtensorMap mA,
    const __grid_constant__ CUtensorMap mB,
    GemmParams p)
{
    extern __shared__ __align__(16) float smem_raw[];
    const int tid = threadIdx.x;
    const int lane = tid & 31;
    const int wid = tid >> 5;
    const int bn = blockIdx.x, bm = blockIdx.y, z = blockIdx.z;
    const size_t coff = (size_t)(z / p.divH) * p.strideCb +
                        (size_t)(z % p.divH) * p.strideCh;

#if defined(__CUDA_ARCH_FEAT_SM103_ALL)
    __shared__ uint32_t s_tmem;
    __shared__ __align__(8) unsigned long long s_mbar[4];  // full0 full1 done0 done1

    const uint32_t raw_u  = smem_u32_g(smem_raw);
    const uint32_t smem_u = (raw_u + 1023u) & ~1023u;   // SW128 atom alignment
    const uint32_t mbar   = smem_u32_g(s_mbar);

    if (wid == 0) { TCGEN05_ALLOC(smem_u32_g(&s_tmem), 256); TCGEN05_RELINQ(); }
    if (tid == 0) {
        MBARRIER_INIT(mbar + 0, 1);  MBARRIER_INIT(mbar + 8, 1);
        MBARRIER_INIT(mbar + 16, 1); MBARRIER_INIT(mbar + 24, 1);
        FENCE_ASYNC();
    }
    __syncthreads();
    const uint32_t tmem = s_tmem;

    // A: 16KB, B: 32KB per stage; 2 stages
    const uint32_t offA0 = smem_u,            offB0 = smem_u + 16384u;
    const uint32_t offA1 = smem_u + 49152u,   offB1 = smem_u + 65536u;
    const int nIter = p.K >> 5;   // 24 / 32 / 288, always even >= 2

    if (wid == 0) {
        if (elect_one()) {
            const CUtensorMap* pA = &mA;
            const CUtensorMap* pB = &mB;
            const int m0 = bm * 128;
            const int n0 = bn * 256;
            int phf0 = 0, phf1 = 0, phd0 = 0, phd1 = 0;

            MBARRIER_EXPECT_TX(mbar + 0, 49152u);
            TMA3D(offA0, pA, 0, m0, z, mbar + 0);
            TMA3D(offB0, pB, 0, n0, z, mbar + 0);

            for (int kt = 0; kt < nIter; kt++) {
                const int buf = kt & 1;
                if (kt + 1 < nIter) {
                    const int nb = buf ^ 1;
                    if (kt >= 1) {   // prior MMA on nb must be done reading
                        if (nb == 0) { MBARRIER_WAIT_PARITY(mbar + 16, phd0); phd0 ^= 1; }
                        else         { MBARRIER_WAIT_PARITY(mbar + 24, phd1); phd1 ^= 1; }
                    }
                    const uint32_t oa = nb ? offA1 : offA0;
                    const uint32_t ob = nb ? offB1 : offB0;
                    MBARRIER_EXPECT_TX(mbar + nb * 8, 49152u);
                    TMA3D(oa, pA, (kt + 1) * 32, m0, z, mbar + nb * 8);
                    TMA3D(ob, pB, (kt + 1) * 32, n0, z, mbar + nb * 8);
                }
                if (buf == 0) { MBARRIER_WAIT_PARITY(mbar + 0, phf0); phf0 ^= 1; }
                else          { MBARRIER_WAIT_PARITY(mbar + 8, phf1); phf1 ^= 1; }
                const uint64_t ad = mk_desc(buf ? offA1 : offA0);
                const uint64_t bd = mk_desc(buf ? offB1 : offB0);
                #pragma unroll
                for (int ks = 0; ks < 4; ks++)
                    mma_tf32_ss(tmem, ad + ks * 2, bd + ks * 2,
                                (kt > 0 || ks > 0) ? 1u : 0u);
                TCGEN05_COMMIT(mbar + 16 + buf * 8);
            }
            MBARRIER_WAIT_PARITY(mbar + 16, phd0);
            MBARRIER_WAIT_PARITY(mbar + 24, phd1);
        }
    }
    __syncthreads();
    TCGEN05_FENCE_AFTER();

    // Epilogue: warp -> rows (wid&3)*32+lane, col half (wid>>2)*128, 32 cols/step
    const int m = bm * 128 + (wid & 3) * 32 + lane;
    const uint32_t cbase = (uint32_t)(wid >> 2) * 128u;
    #pragma unroll
    for (int i = 0; i < 4; i++) {
        uint32_t r[32];
        TCGEN05_LD_32X32B_X32(r, tmem + cbase + i * 32);
        TCGEN05_WAIT_LD();
        const int n0 = bn * 256 + (int)cbase + i * 32;
        float* dst;
        if (EPI == 1) {
            const int b = m >> 10, s = m & 1023;
            const int h = n0 / F3, f = n0 - h * F3;
            dst = &g_qkv[(((size_t)(b * Hn + h)) * Sn + s) * F3 + f];
        } else {
            dst = &p.C[coff + (size_t)m * p.ldc + n0];
        }
        #pragma unroll
        for (int j = 0; j < 32; j += 4) {
            float4 v;
            v.x = __uint_as_float(r[j + 0]) * p.alpha;
            v.y = __uint_as_float(r[j + 1]) * p.alpha;
            v.z = __uint_as_float(r[j + 2]) * p.alpha;
            v.w = __uint_as_float(r[j + 3]) * p.alpha;
            if (p.bias) {
                float4 bb = *(const float4*)&p.bias[n0 + j];
                v.x += bb.x; v.y += bb.y; v.z += bb.z; v.w += bb.w;
            }
            if (ROUND) {
                v.x = __uint_as_float(f2tf32(v.x));
                v.y = __uint_as_float(f2tf32(v.y));
                v.z = __uint_as_float(f2tf32(v.z));
                v.w = __uint_as_float(f2tf32(v.w));
            }
            *(float4*)&dst[j] = v;
        }
    }
    TCGEN05_FENCE_BEFORE();

    __syncthreads();
    if (tid == 0) {
        MBARRIER_INVAL(mbar + 0);  MBARRIER_INVAL(mbar + 8);
        MBARRIER_INVAL(mbar + 16); MBARRIER_INVAL(mbar + 24);
    }
    __syncthreads();
    if (wid == 0) TCGEN05_DEALLOC(tmem, 256);

#else
    // Naive correct fallback (never selected when sm_103a SASS is present)
    (void)smem_raw;
    for (int o = tid; o < 128 * 256; o += 256) {
        const int mi = o >> 8;
        const int ni = o & 255;
        const float* a = p.A + (size_t)z * p.strideAz + (size_t)(bm * 128 + mi) * p.lda;
        const float* b = p.B + (size_t)z * p.strideBz + (size_t)(bn * 256 + ni) * p.ldb;
        float acc = 0.f;
        for (int k = 0; k < p.K; k++) acc += a[k] * b[k];
        float v = acc * p.alpha;
        const int n0 = bn * 256 + ni;
        if (p.bias) v += p.bias[n0];
        if (ROUND) v = __uint_as_float(f2tf32(v));
        const int mg = bm * 128 + mi;
        if (EPI == 1) {
            const int bb = mg >> 10, s = mg & 1023;
            const int h = n0 / F3, f = n0 - h * F3;
            g_qkv[(((size_t)(bb * Hn + h)) * Sn + s) * F3 + f] = v;
        } else {
            p.C[coff + (size_t)mg * p.ldc + n0] = v;
        }
    }
#endif
}

// Round-copy: dst = tf32_rna(src)
__global__ void __launch_bounds__(256) round_copy(const float* __restrict__ s,
                                                  float* __restrict__ d, int n4)
{
    int i = blockIdx.x * blockDim.x + threadIdx.x;
    if (i < n4) {
        float4 v = ((const float4*)s)[i];
        uint4 o;
        o.x = f2tf32(v.x); o.y = f2tf32(v.y); o.z = f2tf32(v.z); o.w = f2tf32(v.w);
        ((uint4*)d)[i] = o;
    }
}

// Transpose V slab of qkv: vT[bh, e, s] = qkv[bh, s, 2E + e] (already rounded)
__global__ void __launch_bounds__(256) transpose_v()
{
    __shared__ float tile[32][33];
    const int bh = blockIdx.z;
    const int s0 = blockIdx.x * 32;
    const int e0 = blockIdx.y * 32;
    const int tx = threadIdx.x;
    const int ty = threadIdx.y;
    const float* src = g_qkv + ((size_t)bh * Sn) * F3 + 2 * En;
    float* dst = g_vT + ((size_t)bh * En) * Sn;

    #pragma unroll
    for (int j = 0; j < 4; j++)
        tile[ty + 8 * j][tx] = src[(size_t)(s0 + ty + 8 * j) * F3 + e0 + tx];
    __syncthreads();
    #pragma unroll
    for (int j = 0; j < 4; j++)
        dst[(size_t)(e0 + ty + 8 * j) * Sn + s0 + tx] = tile[tx][ty + 8 * j];
}

// Softmax rows; output rounded to tf32 bits (AV GEMM input).
__global__ void __launch_bounds__(256) softmax_kernel(float* sc)
{
    float* row = sc + (size_t)blockIdx.x * Sn;
    const int tid = threadIdx.x;
    const int lane = tid & 31;
    const int wid = tid >> 5;
    __shared__ float red[8];

    float4 v = ((const float4*)row)[tid];
    float m = fmaxf(fmaxf(v.x, v.y), fmaxf(v.z, v.w));
    #pragma unroll
    for (int o = 16; o; o >>= 1) m = fmaxf(m, __shfl_xor_sync(~0u, m, o));
    if (lane == 0) red[wid] = m;
    __syncthreads();
    float bm = red[0];
    #pragma unroll
    for (int i = 1; i < 8; i++) bm = fmaxf(bm, red[i]);
    __syncthreads();

    float4 e;
    e.x = __expf(v.x - bm);
    e.y = __expf(v.y - bm);
    e.z = __expf(v.z - bm);
    e.w = __expf(v.w - bm);
    float s = e.x + e.y + e.z + e.w;
    #pragma unroll
    for (int o = 16; o; o >>= 1) s += __shfl_xor_sync(~0u, s, o);
    if (lane == 0) red[wid] = s;
    __syncthreads();
    float bs = red[0];
    #pragma unroll
    for (int i = 1; i < 8; i++) bs += red[i];
    const float rdiv = __frcp_rn(bs);

    uint4 o;
    o.x = f2tf32(e.x * rdiv);
    o.y = f2tf32(e.y * rdiv);
    o.z = f2tf32(e.z * rdiv);
    o.w = f2tf32(e.w * rdiv);
    ((uint4*)row)[tid] = o;
}

#define GEMM_SMEM (98304 + 1024)

// Host-side tensormap builder via driver entry point (no -lcuda needed)
typedef CUresult (*PFN_encodeTM)(CUtensorMap*, CUtensorMapDataType, cuuint32_t, void*,
                                 const cuuint64_t*, const cuuint64_t*, const cuuint32_t*,
                                 const cuuint32_t*, CUtensorMapInterleave, CUtensorMapSwizzle,
                                 CUtensorMapL2promotion, CUtensorMapFloatOOBfill);

static void make_map(CUtensorMap* m, const void* base,
                     unsigned long long d0, unsigned long long d1, unsigned long long d2,
                     unsigned long long s1b, unsigned long long s2b,
                     unsigned int b0, unsigned int b1)
{
    void* fp = nullptr;
    cudaDriverEntryPointQueryResult st;
    cudaGetDriverEntryPoint("cuTensorMapEncodeTiled", &fp, cudaEnableDefault, &st);
    PFN_encodeTM enc = (PFN_encodeTM)fp;
    cuuint64_t dims[3] = {d0, d1, d2};
    cuuint64_t str[2]  = {s1b, s2b};
    cuuint32_t box[3]  = {b0, b1, 1};
    cuuint32_t es[3]   = {1, 1, 1};
    enc(m, CU_TENSOR_MAP_DATA_TYPE_FLOAT32, 3, (void*)base, dims, str, box, es,
        CU_TENSOR_MAP_INTERLEAVE_NONE, CU_TENSOR_MAP_SWIZZLE_128B,
        CU_TENSOR_MAP_L2_PROMOTION_L2_128B, CU_TENSOR_MAP_FLOAT_OOB_FILL_NONE);
}

extern "C" void kernel_launch(void* const* d_in, const int* in_sizes, int n_in,
                              void* d_out, int out_size)
{
    const float* x     = (const float*)d_in[0];  // [B,S,E]
    const float* qkv_w = (const float*)d_in[1];  // [H,3E,E]
    const float* qkv_b = (const float*)d_in[2];  // [H,3E]
    const float* out_w = (const float*)d_in[3];  // [E,H*E]
    const float* out_b = (const float*)d_in[4];  // [E]
    float* out = (float*)d_out;                  // [B,S,E]

    float *qkv, *scores, *vT, *concat, *xr, *wr, *owr;
    cudaGetSymbolAddress((void**)&qkv,    g_qkv);
    cudaGetSymbolAddress((void**)&scores, g_scores);
    cudaGetSymbolAddress((void**)&vT,     g_vT);
    cudaGetSymbolAddress((void**)&concat, g_concat);
    cudaGetSymbolAddress((void**)&xr,     g_xr);
    cudaGetSymbolAddress((void**)&wr,     g_wqkvr);
    cudaGetSymbolAddress((void**)&owr,    g_owr);

    cudaFuncSetAttribute(gemm_tma<1,1>, cudaFuncAttributeMaxDynamicSharedMemorySize, GEMM_SMEM);
    cudaFuncSetAttribute(gemm_tma<0,0>, cudaFuncAttributeMaxDynamicSharedMemorySize, GEMM_SMEM);
    cudaFuncSetAttribute(gemm_tma<0,1>, cudaFuncAttributeMaxDynamicSharedMemorySize, GEMM_SMEM);

    // 0) Pre-round inputs to tf32 bits
    round_copy<<<(Bn*Sn*En/4 + 255)/256, 256>>>(x, xr, Bn*Sn*En/4);
    round_copy<<<(NQKV*En/4 + 255)/256, 256>>>(qkv_w, wr, NQKV*En/4);
    round_copy<<<(En*HE/4 + 255)/256, 256>>>(out_w, owr, En*HE/4);

    // Tensormaps (host-side, capture-safe)
    CUtensorMap mXA, mWB, mQA, mKB, mPA, mVB, mCA, mOB;
    make_map(&mXA, xr,      En, (unsigned long long)Bn*Sn, 1,
             (unsigned long long)En*4, (unsigned long long)Bn*Sn*En*4, 32, 128);
    make_map(&mWB, wr,      En, NQKV, 1,
             (unsigned long long)En*4, (unsigned long long)NQKV*En*4, 32, 256);
    make_map(&mQA, qkv,     En, Sn, Bn*Hn,
             (unsigned long long)F3*4, (unsigned long long)Sn*F3*4, 32, 128);
    make_map(&mKB, qkv+En,  En, Sn, Bn*Hn,
             (unsigned long long)F3*4, (unsigned long long)Sn*F3*4, 32, 256);
    make_map(&mPA, scores,  Sn, Sn, Bn*Hn,
             (unsigned long long)Sn*4, (unsigned long long)Sn*Sn*4, 32, 128);
    make_map(&mVB, vT,      Sn, En, Bn*Hn,
             (unsigned long long)Sn*4, (unsigned long long)En*Sn*4, 32, 256);
    make_map(&mCA, concat,  HE, (unsigned long long)Bn*Sn, 1,
             (unsigned long long)HE*4, (unsigned long long)Bn*Sn*HE*4, 32, 128);
    make_map(&mOB, owr,     HE, En, 1,
             (unsigned long long)HE*4, (unsigned long long)En*HE*4, 32, 256);

    // 1) QKV projection -> scatter [B,H,S,3E], +bias, rounded
    {
        GemmParams p = {};
        p.A = xr; p.B = wr; p.C = qkv;
        p.K = En; p.lda = En; p.ldb = En; p.ldc = 0;
        p.divH = 1; p.bias = qkv_b; p.alpha = 1.0f;
        gemm_tma<1,1><<<dim3(NQKV/256, (Bn*Sn)/128, 1), 256, GEMM_SMEM>>>(mXA, mWB, p);
    }

    // 1b) Transpose V slab -> vT [B*H, E, S]
    transpose_v<<<dim3(Sn/32, En/32, Bn*Hn), dim3(32, 8)>>>();

    // 2) Scores: Q x K^T * scale
    {
        GemmParams p = {};
        p.A = qkv; p.B = qkv + En; p.C = scores;
        p.K = En; p.lda = F3; p.ldb = F3; p.ldc = Sn;
        p.strideAz = (long long)Sn*F3; p.strideBz = (long long)Sn*F3;
        p.strideCb = (long long)Sn*Sn; p.divH = 1;
        p.bias = nullptr; p.alpha = 0.036084391824351615f; // 1/sqrt(768)
        gemm_tma<0,0><<<dim3(Sn/256, Sn/128, Bn*Hn), 256, GEMM_SMEM>>>(mQA, mKB, p);
    }

    // 3) Softmax rows (rounds output)
    softmax_kernel<<<Bn*Hn*Sn, 256>>>(scores);

    // 4) AV: P x vT^T -> concat, rounded
    {
        GemmParams p = {};
        p.A = scores; p.B = vT; p.C = concat;
        p.K = Sn; p.lda = Sn; p.ldb = Sn; p.ldc = HE;
        p.strideAz = (long long)Sn*Sn; p.strideBz = (long long)En*Sn;
        p.strideCb = (long long)Sn*Hn*En; p.strideCh = En; p.divH = Hn;
        p.bias = nullptr; p.alpha = 1.0f;
        gemm_tma<0,1><<<dim3(En/256, Sn/128, Bn*Hn), 256, GEMM_SMEM>>>(mPA, mVB, p);
    }

    // 5) Output projection + bias -> out (full precision)
    {
        GemmParams p = {};
        p.A = concat; p.B = owr; p.C = out;
        p.K = HE; p.lda = HE; p.ldb = HE; p.ldc = En;
        p.divH = 1; p.bias = out_b; p.alpha = 1.0f;
        gemm_tma<0,0><<<dim3(En/256, (Bn*Sn)/128, 1), 256, GEMM_SMEM>>>(mCA, mOB, p);
    }
}